// round 9
// baseline (speedup 1.0000x reference)
#include <cuda_runtime.h>

#define DT 0.005f

// ---------------- scratch (no allocation allowed) ----------------
__device__ float    g_partials[4096];
__device__ unsigned g_sem = 0;
__device__ float4   g_coef[8192];   // fallback path only

// fallback float2 swizzle
__device__ __forceinline__ int swz(int t)  { return t ^ ((t >> 4) & 15); }

// ============================================================================
// Register-resident quarter-row kernel. T=4096 as 4 CTAs x 1024 steps,
// 128 thr x CHUNK=8. NO smem data path:
//  - pass1: per-thread LDG.128 of own 4 pred pairs -> registers (fills L1/L2)
//  - 3-component scan (G,Bx,By) via shuffles; steady constants computed
//    PER-THREAD (sqrt+div, ~3 MUFU warp-instrs) -> no pre-pass1 broadcast
//  - pass2: re-LDG pred (L1 hit) + LDG targ, loss fused inline -> no pass3,
//    no P write-back, ONE __syncthreads in the main path
//  - CTA-entry v via parallel halo dot product (g^64 ~ 2e-10 << 1e-3 tol)
//  - b data-independent: kp* const steady; 12 (Gb,Hb) affines for t<96
// ============================================================================
__global__ void __launch_bounds__(128, 14)
kf_reg(const float* __restrict__ pred, const float* __restrict__ targ,
       const float* __restrict__ qv_p, const float* __restrict__ r_p,
       float* __restrict__ out, int B)
{
    constexpr int NT    = 128;
    constexpr int CHUNK = 8;             // steps per thread
    constexpr int NPAIR = 512;           // pairs per CTA (1024 timesteps)
    constexpr int TTR   = 96;            // transient length
    constexpr int NTC   = TTR / CHUNK;   // 12 transient chunks

    __shared__ float4 s_tc[TTR];         // transient (g, kv, u, inv)
    __shared__ float2 s_tb[NTC];         // per-chunk b-affine (Gb, Hb)
    __shared__ float2 s_vinit;
    __shared__ float  sWG[4], sWBx[4], sWBy[4];
    __shared__ float  sred[4];
    __shared__ float  sf[128];
    __shared__ int    s_last;

    const int j    = threadIdx.x;
    const int blk  = blockIdx.x;
    const int row  = blk >> 2;
    const int qtr  = blk & 3;
    const int lane = j & 31;
    const int wrp  = j >> 5;

    const float qv = __ldg(qv_p);
    const float r  = __ldg(r_p);

    // ---- steady-state gains, per-thread (cheap: ~3 MUFU warp-instrs) ----
    const float cstar = 0.5f * (sqrtf(fmaf(qv, qv, 4.f * r * qv)) - qv);
    const float cps   = cstar + qv;
    const float invs  = 1.0f / (cps + r);
    const float kvs   = cps * invs;
    const float gs    = 1.0f - kvs;
    const float us    = DT * cstar * invs;
    const float kps   = us / kvs;        // kp* = u*/(1-g*)
    const float g2 = gs * gs, g4 = g2 * g2, g8 = g4 * g4;

    // per-thread data pointers: thread j owns pairs [4j, 4j+4) of its quarter
    const float4* gp = (const float4*)pred + (size_t)row * 2048 + qtr * NPAIR + 4 * j;
    const float4* gt = (const float4*)targ + (size_t)row * 2048 + qtr * NPAIR + 4 * j;

    const bool trans = (qtr == 0) && (j < NTC);

    // ---- transient gain table + per-chunk b-affine (qtr 0, j<12) ----
    if (trans) {
        const float r64   = 64.f * r;
        const float rqv64 = 64.f * r * qv;
        const float qvr   = qv + r;
        const float qvr64 = 64.f * qvr;
        const int tstart  = j * CHUNK;
        float p = 1.f, q = 1.f;                       // c0 = 1
        for (int s = 0; s < tstart; ++s) {
            float pn = fmaf(r64, p, rqv64 * q);
            float qn = fmaf(qvr64, q, 64.f * p);
            p = pn; q = qn;
        }
        float Gb = 1.f, Hb = 0.f;                     // b' = g*b + r*u
        #pragma unroll
        for (int i = 0; i < CHUNK; ++i) {
            float num  = fmaf(qv,  q, p);
            float den  = fmaf(qvr, q, p);
            float invd = 1.0f / den;
            float kv   = num * invd;
            float inv  = q * invd;
            float u    = DT * p * invd;
            float g    = 1.0f - kv;
            s_tc[tstart + i] = make_float4(g, kv, u, inv);
            Hb = fmaf(g, Hb, r * u);
            Gb *= g;
            float pn = fmaf(r64, p, rqv64 * q);
            float qn = fmaf(qvr64, q, 64.f * p);
            p = pn; q = qn;
        }
        s_tb[j] = make_float2(Gb, Hb);
    }

    // ---- CTA-entry v: parallel halo dot product (warp 0) ----
    if (qtr != 0) {
        if (wrp == 0) {
            const float4* gh = (const float4*)pred + (size_t)row * 2048
                             + qtr * NPAIR - 32 + lane;
            float4 Z = gh[0];
            float lg = log2f(gs);
            float e0 = (float)(63 - 2 * lane);
            float w0 = kvs * exp2f(e0 * lg);
            float w1 = kvs * exp2f((e0 - 1.f) * lg);
            float hx = fmaf(w0, Z.x, w1 * Z.z);
            float hy = fmaf(w0, Z.y, w1 * Z.w);
            #pragma unroll
            for (int o = 16; o; o >>= 1) {
                hx += __shfl_down_sync(0xffffffffu, hx, o);
                hy += __shfl_down_sync(0xffffffffu, hy, o);
            }
            if (lane == 0) s_vinit = make_float2(hx, hy);
        }
    } else if (j == 0) {
        s_vinit = make_float2(0.f, 0.f);
    }

    // ---- pass 1: LDG own 4 pred pairs, local v-affine ----
    float4 Z0 = gp[0], Z1 = gp[1], Z2 = gp[2], Z3 = gp[3];
    float G, Bx = 0.f, By = 0.f;
    if (trans) {
        G = 1.f;
        const int t0 = j * CHUNK;
        #pragma unroll
        for (int i = 0; i < 4; ++i) {
            float4 Z  = (i == 0) ? Z0 : (i == 1) ? Z1 : (i == 2) ? Z2 : Z3;
            float4 c0 = s_tc[t0 + 2 * i];
            float4 c1 = s_tc[t0 + 2 * i + 1];
            Bx = fmaf(c0.x, Bx, c0.y * Z.x);
            By = fmaf(c0.x, By, c0.y * Z.y);
            Bx = fmaf(c1.x, Bx, c1.y * Z.z);
            By = fmaf(c1.x, By, c1.y * Z.w);
            G *= c0.x * c1.x;
        }
    } else {
        G = g8;
        #pragma unroll
        for (int i = 0; i < 4; ++i) {
            float4 Z = (i == 0) ? Z0 : (i == 1) ? Z1 : (i == 2) ? Z2 : Z3;
            Bx = fmaf(gs, Bx, kvs * Z.x);
            By = fmaf(gs, By, kvs * Z.y);
            Bx = fmaf(gs, Bx, kvs * Z.z);
            By = fmaf(gs, By, kvs * Z.w);
        }
    }

    // ---- 3-component intra-warp scan + warp partials ----
    #pragma unroll
    for (int off = 1; off < 32; off <<= 1) {
        float pG  = __shfl_up_sync(0xffffffffu, G,  off);
        float pBx = __shfl_up_sync(0xffffffffu, Bx, off);
        float pBy = __shfl_up_sync(0xffffffffu, By, off);
        if (lane >= off) {
            Bx = fmaf(G, pBx, Bx);
            By = fmaf(G, pBy, By);
            G *= pG;
        }
    }
    float eG  = __shfl_up_sync(0xffffffffu, G,  1);
    float eBx = __shfl_up_sync(0xffffffffu, Bx, 1);
    float eBy = __shfl_up_sync(0xffffffffu, By, 1);
    if (lane == 0) { eG = 1.f; eBx = 0.f; eBy = 0.f; }
    if (lane == 31) { sWG[wrp] = G; sWBx[wrp] = Bx; sWBy[wrp] = By; }
    __syncthreads();                         // [B] partials + v_init + tables

    // ---- fold previous warps' partials, then own exclusive ----
    float Gp = 1.f, Bpx = 0.f, Bpy = 0.f;
    #pragma unroll
    for (int k = 0; k < 3; ++k) {
        if (k < wrp) {
            Bpx = fmaf(sWG[k], Bpx, sWBx[k]);
            Bpy = fmaf(sWG[k], Bpy, sWBy[k]);
            Gp *= sWG[k];
        }
    }
    float Ge  = eG * Gp;
    float2 vi = s_vinit;
    float vx = fmaf(Ge, vi.x, fmaf(eG, Bpx, eBx));   // v at chunk entry
    float vy = fmaf(Ge, vi.y, fmaf(eG, Bpy, eBy));

    // ---- pass 2: re-LDG pred (L1 hit) + targ, fused loss ----
    float acc = 0.f;
    if (trans) {
        float b = 0.f;
        #pragma unroll
        for (int k = 0; k < NTC - 1; ++k) {
            if (k < j) { float2 tb = s_tb[k]; b = fmaf(tb.x, b, tb.y); }
        }
        const int t0 = j * CHUNK;
        #pragma unroll
        for (int i = 0; i < 4; ++i) {
            float4 Z  = gp[i];
            float4 W  = gt[i];
            float4 c0 = s_tc[t0 + 2 * i];
            float4 c1 = s_tc[t0 + 2 * i + 1];
            float kp0 = fmaf(b, c0.w, c0.z);  b = r * kp0;
            float dx0 = Z.x - vx, dy0 = Z.y - vy;
            if (j != 0 || i != 0) {          // global t = 0 has no loss term
                float ex = fmaf(-DT, W.x, fmaf(kp0, dx0, DT * vx));
                float ey = fmaf(-DT, W.y, fmaf(kp0, dy0, DT * vy));
                acc = fmaf(ex, ex, fmaf(ey, ey, acc));
            }
            vx = fmaf(c0.y, dx0, vx); vy = fmaf(c0.y, dy0, vy);
            float kp1 = fmaf(b, c1.w, c1.z);  b = r * kp1;
            float dx1 = Z.z - vx, dy1 = Z.w - vy;
            float ex1 = fmaf(-DT, W.z, fmaf(kp1, dx1, DT * vx));
            float ey1 = fmaf(-DT, W.w, fmaf(kp1, dy1, DT * vy));
            acc = fmaf(ex1, ex1, fmaf(ey1, ey1, acc));
            vx = fmaf(c1.y, dx1, vx); vy = fmaf(c1.y, dy1, vy);
        }
    } else {
        #pragma unroll
        for (int i = 0; i < 4; ++i) {
            float4 Z = gp[i];
            float4 W = gt[i];
            float dx0 = Z.x - vx, dy0 = Z.y - vy;
            float ex0 = fmaf(-DT, W.x, fmaf(kps, dx0, DT * vx));
            float ey0 = fmaf(-DT, W.y, fmaf(kps, dy0, DT * vy));
            acc = fmaf(ex0, ex0, fmaf(ey0, ey0, acc));
            vx = fmaf(kvs, dx0, vx); vy = fmaf(kvs, dy0, vy);
            float dx1 = Z.z - vx, dy1 = Z.w - vy;
            float ex1 = fmaf(-DT, W.z, fmaf(kps, dx1, DT * vx));
            float ey1 = fmaf(-DT, W.w, fmaf(kps, dy1, DT * vy));
            acc = fmaf(ex1, ex1, fmaf(ey1, ey1, acc));
            vx = fmaf(kvs, dx1, vx); vy = fmaf(kvs, dy1, vy);
        }
    }

    // ---- block reduce -> partial ----
    #pragma unroll
    for (int o = 16; o; o >>= 1) acc += __shfl_down_sync(0xffffffffu, acc, o);
    if (lane == 0) sred[wrp] = acc;
    __syncthreads();
    if (j == 0) {
        float v = sred[0] + sred[1] + sred[2] + sred[3];
        g_partials[blk] = v;
        __threadfence();
        unsigned done = atomicAdd(&g_sem, 1u);
        s_last = (done == (unsigned)gridDim.x - 1u);
    }
    __syncthreads();

    // ---- last CTA: deterministic final reduction + semaphore reset ----
    if (s_last) {
        __threadfence();
        const int nblk = 4 * B;
        float v = 0.f;
        for (int i = j; i < nblk; i += NT) v += g_partials[i];
        sf[j] = v;
        __syncthreads();
        for (int o = 64; o; o >>= 1) {
            if (j < o) sf[j] += sf[j + o];
            __syncthreads();
        }
        if (j == 0) {
            out[0] = sf[0] / ((float)B * 4095.0f * 2.f);
            atomicExch(&g_sem, 0u);
        }
    }
}

// ============================================================================
// Fallback path (any T) — proven Round-1 kernels
// ============================================================================
__global__ void kf_setup(const float* __restrict__ q_vel_p,
                         const float* __restrict__ r_vel_p, int T) {
    __shared__ float skp[4096];
    __shared__ float skv[4096];
    __shared__ int   s_conv;
    __shared__ float s_kp_last, s_kv_last;

    int Tser = T < 4096 ? T : 4096;
    if (threadIdx.x == 0) {
        float qvv = *q_vel_p;
        float rr  = *r_vel_p;
        float bb = 0.f, cc = 1.f;
        float kp = 0.f, kv = 0.f;
        int tconv = Tser;
        for (int t = 0; t < Tser; ++t) {
            float cp  = cc + qvv;
            float bp  = fmaf(DT, cc, bb);
            float S   = cp + rr;
            float inv = __fdividef(1.f, S);
            kv = cp * inv;
            kp = bp * inv;
            skp[t] = kp; skv[t] = kv;
            float rs = rr * inv;
            float nc = cp * rs;
            float nb = bp * rs;
            if (nc == cc && nb == bb) { tconv = t + 1; break; }
            cc = nc; bb = nb;
        }
        s_conv = tconv; s_kp_last = kp; s_kv_last = kv;
    }
    __syncthreads();
    int   tconv = s_conv;
    float kpl = s_kp_last, kvl = s_kv_last;
    for (int t = threadIdx.x; t < T; t += blockDim.x) {
        float kp = (t < tconv) ? skp[t] : kpl;
        float kv = (t < tconv) ? skv[t] : kvl;
        g_coef[t] = make_float4(1.f - kv, kv, DT - kp, kp);
    }
}

__global__ void __launch_bounds__(256)
kf_main(const float* __restrict__ pred, const float* __restrict__ targ, int T) {
    extern __shared__ float2 sp2[];
    const int NT = 256;
    int j = threadIdx.x, bb = blockIdx.x;

    const float4* gp = (const float4*)(pred + (size_t)bb * T * 2);
    int n4 = (T * 2) / 4;
    for (int m = j; m < n4; m += NT) {
        float4 v = gp[m];
        sp2[swz(2 * m)]     = make_float2(v.x, v.y);
        sp2[swz(2 * m + 1)] = make_float2(v.z, v.w);
    }
    __syncthreads();

    int chunk = (T + NT - 1) / NT;
    int t0 = j * chunk;

    float A = 1.f, Bx = 0.f, By = 0.f;
    for (int i = 0; i < chunk; ++i) {
        int t = t0 + i;
        if (t >= T) break;
        float4 cf = g_coef[t];
        float2 z  = sp2[swz(t)];
        A  = A * cf.x;
        Bx = fmaf(cf.x, Bx, cf.y * z.x);
        By = fmaf(cf.x, By, cf.y * z.y);
    }

    __shared__ float sA[256], sBx[256], sBy[256];
    sA[j] = A; sBx[j] = Bx; sBy[j] = By;
    __syncthreads();
    for (int off = 1; off < NT; off <<= 1) {
        float a2 = 0.f, bx2 = 0.f, by2 = 0.f;
        bool act = (j >= off);
        if (act) {
            float ap = sA[j - off], bxp = sBx[j - off], byp = sBy[j - off];
            a2  = A * ap;
            bx2 = fmaf(A, bxp, Bx);
            by2 = fmaf(A, byp, By);
        }
        __syncthreads();
        if (act) { A = a2; Bx = bx2; By = by2; sA[j] = A; sBx[j] = Bx; sBy[j] = By; }
        __syncthreads();
    }
    float vx = (j == 0) ? 0.f : sBx[j - 1];
    float vy = (j == 0) ? 0.f : sBy[j - 1];

    const float2* gt2 = (const float2*)(targ + (size_t)bb * T * 2);
    float acc = 0.f;
    for (int i = 0; i < chunk; ++i) {
        int t = t0 + i;
        if (t >= T) break;
        float4 cf = g_coef[t];
        float2 z  = sp2[swz(t)];
        if (t > 0) {
            float2 w = gt2[t];
            float ex = fmaf(cf.z, vx, fmaf(cf.w, z.x, -DT * w.x));
            float ey = fmaf(cf.z, vy, fmaf(cf.w, z.y, -DT * w.y));
            acc = fmaf(ex, ex, fmaf(ey, ey, acc));
        }
        vx = fmaf(cf.x, vx, cf.y * z.x);
        vy = fmaf(cf.x, vy, cf.y * z.y);
    }

    for (int o = 16; o; o >>= 1) acc += __shfl_down_sync(0xffffffffu, acc, o);
    __shared__ float swsum[8];
    if ((j & 31) == 0) swsum[j >> 5] = acc;
    __syncthreads();
    if (j < 8) {
        float v = swsum[j];
        v += __shfl_down_sync(0xffu, v, 4);
        v += __shfl_down_sync(0xffu, v, 2);
        v += __shfl_down_sync(0xffu, v, 1);
        if (j == 0) g_partials[bb] = v;
    }
}

__global__ void kf_reduce(float* __restrict__ out, int B, int T) {
    __shared__ float s[256];
    float v = 0.f;
    for (int i = threadIdx.x; i < B; i += blockDim.x) v += g_partials[i];
    s[threadIdx.x] = v;
    __syncthreads();
    for (int o = 128; o; o >>= 1) {
        if (threadIdx.x < o) s[threadIdx.x] += s[threadIdx.x + o];
        __syncthreads();
    }
    if (threadIdx.x == 0)
        out[0] = s[0] / ((float)B * (float)(T - 1) * 2.f);
}

extern "C" void kernel_launch(void* const* d_in, const int* in_sizes, int n_in,
                              void* d_out, int out_size) {
    // metadata order: pred_vel, targ_vel, q_pos, q_vel, r_vel, p0
    const float* pred  = (const float*)d_in[0];
    const float* targ  = (const float*)d_in[1];
    const float* q_vel = (const float*)d_in[3];
    const float* r_vel = (const float*)d_in[4];
    int B = in_sizes[5] / 2;          // p0 is (B, 2)
    int T = in_sizes[0] / (B * 2);    // pred_vel is (B, T, 2)

    if (T == 4096 && B >= 1 && B <= 1024) {
        kf_reg<<<4 * B, 128>>>(pred, targ, q_vel, r_vel, (float*)d_out, B);
    } else {
        kf_setup<<<1, 256>>>(q_vel, r_vel, T);
        size_t sh = (size_t)T * sizeof(float2);
        kf_main<<<B, 256, sh>>>(pred, targ, T);
        kf_reduce<<<1, 256>>>((float*)d_out, B, T);
    }
}

// round 10
// speedup vs baseline: 1.3145x; 1.3145x over previous
#include <cuda_runtime.h>

#define DT 0.005f

// ---------------- scratch (no allocation allowed) ----------------
__device__ float    g_partials[4096];
__device__ unsigned g_sem = 0;
__device__ float4   g_coef[8192];   // fallback path only

// fallback float2 swizzle
__device__ __forceinline__ int swz(int t)  { return t ^ ((t >> 4) & 15); }
// float4 swizzle
__device__ __forceinline__ int swz4(int s) { return s ^ ((s >> 3) & 7); }

__device__ __forceinline__ void cp16(unsigned dst, const void* src) {
    asm volatile("cp.async.cg.shared.global [%0], [%1], 16;\n" :: "r"(dst), "l"(src));
}
__device__ __forceinline__ void cp_commit() { asm volatile("cp.async.commit_group;\n"); }
template <int N>
__device__ __forceinline__ void cp_wait() { asm volatile("cp.async.wait_group %0;\n" :: "n"(N)); }

// ============================================================================
// Split-row scan kernel, pass2-free. T=4096 as 2 CTAs x 2048 steps,
// 128 thr x CHUNK=16. vs R6: the full replay pass is deleted algebraically:
//   pass1 writes Ploc = kp*z + dkp*v_loc in place of z (v_loc = running
//   pass-1 accumulator); after the scan each thread publishes its entry
//   state v_e; pass3 reconstructs P = Ploc + dkp*g^i * v_e with per-thread
//   constant weights (local pair index j&7 is k-invariant since 128%8==0).
// Transient (6 threads of first CTA per row) keeps the exact replay, v_e=0.
//  - CTA-entry v via parallel halo dot product (g^64 ~ 2e-10 << 1e-3 tol)
//  - 3-component scan (G, Bx, By); steady constants computed per-thread
// ============================================================================
__global__ void __launch_bounds__(128, 8)
kf_split(const float* __restrict__ pred, const float* __restrict__ targ,
         const float* __restrict__ qv_p, const float* __restrict__ r_p,
         float* __restrict__ out, int B)
{
    constexpr int NT    = 128;
    constexpr int CHUNK = 16;
    constexpr int NPREF = 32;            // halo pairs (64 timesteps)
    constexpr int NPAIR = 1024;          // main pairs (2048 timesteps)
    constexpr int TTR   = 96;            // transient gain length
    constexpr int NTC   = TTR / CHUNK;   // 6 transient chunks

    __shared__ float4 sz4[NPAIR + NPREF];   // [0,32) halo, [32,1056) main: z -> Ploc/P
    __shared__ float4 s_tc[TTR];            // transient (g, kv, u, inv)
    __shared__ float2 s_tb[NTC];            // per-chunk b-affine (Gb, Hb)
    __shared__ float2 s_ve[NT];             // per-chunk entry state v_e
    __shared__ float2 s_vinit;              // halo-derived CTA entry v
    __shared__ float  sWG[4], sWBx[4], sWBy[4];
    __shared__ float  sred[4];
    __shared__ float  sf[128];
    __shared__ int    s_last;

    const int j    = threadIdx.x;
    const int blk  = blockIdx.x;
    const int row  = blk >> 1;
    const int half = blk & 1;
    const int lane = j & 31;
    const int wrp  = j >> 5;

    const float qv = __ldg(qv_p);
    const float r  = __ldg(r_p);

    const unsigned sa = (unsigned)__cvta_generic_to_shared(sz4);

    // ---- async stage: pred pairs (+ halo prefix for half 1) ----
    const float4* gp4 = (const float4*)pred + (size_t)row * 2048;
    if (half == 0) {
        #pragma unroll
        for (int k = 0; k < 8; ++k) {
            int m = j + k * NT;
            cp16(sa + 16u * (unsigned)swz4(m + NPREF), gp4 + m);
        }
    } else {
        const float4* gh = gp4 + (NPAIR - NPREF);   // global pair 992
        #pragma unroll
        for (int k = 0; k < 8; ++k) {
            int lp = j + k * NT;
            cp16(sa + 16u * (unsigned)swz4(lp), gh + lp);
        }
        if (j < NPREF) cp16(sa + 16u * (unsigned)swz4(NPAIR + j), gh + NPAIR + j);
    }
    cp_commit();

    // ---- steady-state constants, per-thread (few MUFU warp-instrs) ----
    const float cstar = 0.5f * (sqrtf(fmaf(qv, qv, 4.f * r * qv)) - qv);
    const float cps   = cstar + qv;
    const float invs  = 1.0f / (cps + r);
    const float kvs   = cps * invs;
    const float gs    = 1.0f - kvs;
    const float us    = DT * cstar * invs;
    const float kps   = us / kvs;            // kp* = u*/(1-g*)
    const float dkp   = DT - kps;
    const float gg2 = gs * gs, gg4 = gg2 * gg2, gg8 = gg4 * gg4;
    const float g16 = gg8 * gg8;

    const bool trans = (half == 0) && (j < NTC);

    // ---- transient gain table + per-chunk b-affine (half 0, j<6) ----
    if (trans) {
        const float r64   = 64.f * r;
        const float rqv64 = 64.f * r * qv;
        const float qvr   = qv + r;
        const float qvr64 = 64.f * qvr;
        const int tstart  = j * CHUNK;
        float p = 1.f, q = 1.f;                       // c0 = 1
        for (int s = 0; s < tstart; ++s) {
            float pn = fmaf(r64, p, rqv64 * q);
            float qn = fmaf(qvr64, q, 64.f * p);
            p = pn; q = qn;
        }
        float Gb = 1.f, Hb = 0.f;                     // b' = g*b + r*u
        #pragma unroll
        for (int i = 0; i < CHUNK; ++i) {
            float num  = fmaf(qv,  q, p);
            float den  = fmaf(qvr, q, p);
            float invd = 1.0f / den;
            float kv   = num * invd;
            float inv  = q * invd;
            float u    = DT * p * invd;
            float g    = 1.0f - kv;
            s_tc[tstart + i] = make_float4(g, kv, u, inv);
            Hb = fmaf(g, Hb, r * u);
            Gb *= g;
            float pn = fmaf(r64, p, rqv64 * q);
            float qn = fmaf(qvr64, q, 64.f * p);
            p = pn; q = qn;
        }
        s_tb[j] = make_float2(Gb, Hb);
    }
    if (j == 0) s_vinit = make_float2(0.f, 0.f);

    cp_wait<0>();
    __syncthreads();                         // [A] data + tables ready

    const int p0 = NPREF + 8 * j;            // first local pair of my chunk

    // ---- half 1: parallel halo dot product on warp 0 ----
    if (half == 1 && wrp == 0) {
        float lg = log2f(gs);
        float e0 = (float)(63 - 2 * lane);
        float w0 = kvs * exp2f(e0 * lg);
        float w1 = kvs * exp2f((e0 - 1.f) * lg);
        float4 Z = sz4[swz4(lane)];
        float hx = fmaf(w0, Z.x, w1 * Z.z);
        float hy = fmaf(w0, Z.y, w1 * Z.w);
        #pragma unroll
        for (int o = 16; o; o >>= 1) {
            hx += __shfl_down_sync(0xffffffffu, hx, o);
            hy += __shfl_down_sync(0xffffffffu, hy, o);
        }
        if (lane == 0) s_vinit = make_float2(hx, hy);
    }

    // ---- pass 1: local v-affine; steady threads also emit Ploc in place ----
    float G, Bx = 0.f, By = 0.f;
    if (trans) {
        G = 1.f;
        const int t0 = j * CHUNK;
        #pragma unroll
        for (int i = 0; i < 8; ++i) {
            float4 Z  = sz4[swz4(p0 + i)];
            float4 c0 = s_tc[t0 + 2 * i];
            float4 c1 = s_tc[t0 + 2 * i + 1];
            Bx = fmaf(c0.x, Bx, c0.y * Z.x);
            By = fmaf(c0.x, By, c0.y * Z.y);
            Bx = fmaf(c1.x, Bx, c1.y * Z.z);
            By = fmaf(c1.x, By, c1.y * Z.w);
            G *= c0.x * c1.x;
        }
    } else {
        G = g16;
        #pragma unroll
        for (int i = 0; i < 8; ++i) {
            float4 Z = sz4[swz4(p0 + i)];
            float P0x = fmaf(kps, Z.x, dkp * Bx);    // uses v_loc BEFORE step
            float P0y = fmaf(kps, Z.y, dkp * By);
            Bx = fmaf(gs, Bx, kvs * Z.x);
            By = fmaf(gs, By, kvs * Z.y);
            float P1x = fmaf(kps, Z.z, dkp * Bx);
            float P1y = fmaf(kps, Z.w, dkp * By);
            Bx = fmaf(gs, Bx, kvs * Z.z);
            By = fmaf(gs, By, kvs * Z.w);
            sz4[swz4(p0 + i)] = make_float4(P0x, P0y, P1x, P1y);
        }
    }

    // ---- 3-component scan: intra-warp inclusive + warp fold ----
    #pragma unroll
    for (int off = 1; off < 32; off <<= 1) {
        float pG  = __shfl_up_sync(0xffffffffu, G,  off);
        float pBx = __shfl_up_sync(0xffffffffu, Bx, off);
        float pBy = __shfl_up_sync(0xffffffffu, By, off);
        if (lane >= off) {
            Bx = fmaf(G, pBx, Bx);
            By = fmaf(G, pBy, By);
            G *= pG;
        }
    }
    float eG  = __shfl_up_sync(0xffffffffu, G,  1);
    float eBx = __shfl_up_sync(0xffffffffu, Bx, 1);
    float eBy = __shfl_up_sync(0xffffffffu, By, 1);
    if (lane == 0) { eG = 1.f; eBx = 0.f; eBy = 0.f; }
    if (lane == 31) { sWG[wrp] = G; sWBx[wrp] = Bx; sWBy[wrp] = By; }
    __syncthreads();                         // [B] warp partials + v_init ready

    float Gp = 1.f, Bpx = 0.f, Bpy = 0.f;
    #pragma unroll
    for (int k = 0; k < 3; ++k) {
        if (k < wrp) {
            Bpx = fmaf(sWG[k], Bpx, sWBx[k]);
            Bpy = fmaf(sWG[k], Bpy, sWBy[k]);
            Gp *= sWG[k];
        }
    }
    float Ge  = eG * Gp;
    float2 vi = s_vinit;
    float vx = fmaf(Ge, vi.x, fmaf(eG, Bpx, eBx));   // v at chunk entry
    float vy = fmaf(Ge, vi.y, fmaf(eG, Bpy, eBy));

    // ---- publish entry state; transient does exact replay (writes P) ----
    if (trans) {
        s_ve[j] = make_float2(0.f, 0.f);
        float b = 0.f;
        #pragma unroll
        for (int k = 0; k < NTC - 1; ++k) {
            if (k < j) { float2 tb = s_tb[k]; b = fmaf(tb.x, b, tb.y); }
        }
        const int t0 = j * CHUNK;
        #pragma unroll
        for (int i = 0; i < 8; ++i) {
            float4 Z  = sz4[swz4(p0 + i)];
            float4 c0 = s_tc[t0 + 2 * i];
            float4 c1 = s_tc[t0 + 2 * i + 1];
            float kp0 = fmaf(b, c0.w, c0.z);  b = r * kp0;
            float dx0 = Z.x - vx, dy0 = Z.y - vy;
            float Px0 = fmaf(kp0, dx0, DT * vx);
            float Py0 = fmaf(kp0, dy0, DT * vy);
            vx = fmaf(c0.y, dx0, vx); vy = fmaf(c0.y, dy0, vy);
            float kp1 = fmaf(b, c1.w, c1.z);  b = r * kp1;
            float dx1 = Z.z - vx, dy1 = Z.w - vy;
            float Px1 = fmaf(kp1, dx1, DT * vx);
            float Py1 = fmaf(kp1, dy1, DT * vy);
            vx = fmaf(c1.y, dx1, vx); vy = fmaf(c1.y, dy1, vy);
            sz4[swz4(p0 + i)] = make_float4(Px0, Py0, Px1, Py1);
        }
    } else {
        s_ve[j] = make_float2(vx, vy);
    }
    __syncthreads();                         // [C] P/Ploc + v_e ready

    // ---- pass 3: coalesced targ; P = Ploc + w*v_e; loss ----
    const float4* gt = (const float4*)targ + (size_t)row * 2048
                     + (size_t)half * NPAIR;
    const int   lp  = j & 7;                 // k-invariant local pair index
    const float lg2 = log2f(gs);
    const float w0  = dkp * exp2f(lg2 * (float)(2 * lp));   // dkp*g^(2lp)
    const float w1  = w0 * gs;
    float acc = 0.f;
    #pragma unroll
    for (int k = 0; k < 8; ++k) {
        int m = j + k * NT;
        float4 W  = gt[m];
        float4 P  = sz4[swz4(NPREF + m)];
        float2 ve = s_ve[(j >> 3) + k * 16];
        float Px0 = fmaf(w0, ve.x, P.x);
        float Py0 = fmaf(w0, ve.y, P.y);
        float Px1 = fmaf(w1, ve.x, P.z);
        float Py1 = fmaf(w1, ve.y, P.w);
        if (half != 0 || m != 0) {           // t = 0 has no loss term
            float ex = fmaf(-DT, W.x, Px0);
            float ey = fmaf(-DT, W.y, Py0);
            acc = fmaf(ex, ex, fmaf(ey, ey, acc));
        }
        float ex1 = fmaf(-DT, W.z, Px1);
        float ey1 = fmaf(-DT, W.w, Py1);
        acc = fmaf(ex1, ex1, fmaf(ey1, ey1, acc));
    }

    // ---- block reduce -> partial ----
    #pragma unroll
    for (int o = 16; o; o >>= 1) acc += __shfl_down_sync(0xffffffffu, acc, o);
    if (lane == 0) sred[wrp] = acc;
    __syncthreads();
    if (j == 0) {
        float v = sred[0] + sred[1] + sred[2] + sred[3];
        g_partials[blk] = v;
        __threadfence();
        unsigned done = atomicAdd(&g_sem, 1u);
        s_last = (done == (unsigned)gridDim.x - 1u);
    }
    __syncthreads();

    // ---- last CTA: deterministic final reduction + semaphore reset ----
    if (s_last) {
        __threadfence();
        const int nblk = 2 * B;
        float v = 0.f;
        for (int i = j; i < nblk; i += NT) v += g_partials[i];
        sf[j] = v;
        __syncthreads();
        for (int o = 64; o; o >>= 1) {
            if (j < o) sf[j] += sf[j + o];
            __syncthreads();
        }
        if (j == 0) {
            out[0] = sf[0] / ((float)B * 4095.0f * 2.f);
            atomicExch(&g_sem, 0u);
        }
    }
}

// ============================================================================
// Fallback path (any T) — proven Round-1 kernels
// ============================================================================
__global__ void kf_setup(const float* __restrict__ q_vel_p,
                         const float* __restrict__ r_vel_p, int T) {
    __shared__ float skp[4096];
    __shared__ float skv[4096];
    __shared__ int   s_conv;
    __shared__ float s_kp_last, s_kv_last;

    int Tser = T < 4096 ? T : 4096;
    if (threadIdx.x == 0) {
        float qvv = *q_vel_p;
        float rr  = *r_vel_p;
        float bb = 0.f, cc = 1.f;
        float kp = 0.f, kv = 0.f;
        int tconv = Tser;
        for (int t = 0; t < Tser; ++t) {
            float cp  = cc + qvv;
            float bp  = fmaf(DT, cc, bb);
            float S   = cp + rr;
            float inv = __fdividef(1.f, S);
            kv = cp * inv;
            kp = bp * inv;
            skp[t] = kp; skv[t] = kv;
            float rs = rr * inv;
            float nc = cp * rs;
            float nb = bp * rs;
            if (nc == cc && nb == bb) { tconv = t + 1; break; }
            cc = nc; bb = nb;
        }
        s_conv = tconv; s_kp_last = kp; s_kv_last = kv;
    }
    __syncthreads();
    int   tconv = s_conv;
    float kpl = s_kp_last, kvl = s_kv_last;
    for (int t = threadIdx.x; t < T; t += blockDim.x) {
        float kp = (t < tconv) ? skp[t] : kpl;
        float kv = (t < tconv) ? skv[t] : kvl;
        g_coef[t] = make_float4(1.f - kv, kv, DT - kp, kp);
    }
}

__global__ void __launch_bounds__(256)
kf_main(const float* __restrict__ pred, const float* __restrict__ targ, int T) {
    extern __shared__ float2 sp2[];
    const int NT = 256;
    int j = threadIdx.x, bb = blockIdx.x;

    const float4* gp = (const float4*)(pred + (size_t)bb * T * 2);
    int n4 = (T * 2) / 4;
    for (int m = j; m < n4; m += NT) {
        float4 v = gp[m];
        sp2[swz(2 * m)]     = make_float2(v.x, v.y);
        sp2[swz(2 * m + 1)] = make_float2(v.z, v.w);
    }
    __syncthreads();

    int chunk = (T + NT - 1) / NT;
    int t0 = j * chunk;

    float A = 1.f, Bx = 0.f, By = 0.f;
    for (int i = 0; i < chunk; ++i) {
        int t = t0 + i;
        if (t >= T) break;
        float4 cf = g_coef[t];
        float2 z  = sp2[swz(t)];
        A  = A * cf.x;
        Bx = fmaf(cf.x, Bx, cf.y * z.x);
        By = fmaf(cf.x, By, cf.y * z.y);
    }

    __shared__ float sA[256], sBx[256], sBy[256];
    sA[j] = A; sBx[j] = Bx; sBy[j] = By;
    __syncthreads();
    for (int off = 1; off < NT; off <<= 1) {
        float a2 = 0.f, bx2 = 0.f, by2 = 0.f;
        bool act = (j >= off);
        if (act) {
            float ap = sA[j - off], bxp = sBx[j - off], byp = sBy[j - off];
            a2  = A * ap;
            bx2 = fmaf(A, bxp, Bx);
            by2 = fmaf(A, byp, By);
        }
        __syncthreads();
        if (act) { A = a2; Bx = bx2; By = by2; sA[j] = A; sBx[j] = Bx; sBy[j] = By; }
        __syncthreads();
    }
    float vx = (j == 0) ? 0.f : sBx[j - 1];
    float vy = (j == 0) ? 0.f : sBy[j - 1];

    const float2* gt2 = (const float2*)(targ + (size_t)bb * T * 2);
    float acc = 0.f;
    for (int i = 0; i < chunk; ++i) {
        int t = t0 + i;
        if (t >= T) break;
        float4 cf = g_coef[t];
        float2 z  = sp2[swz(t)];
        if (t > 0) {
            float2 w = gt2[t];
            float ex = fmaf(cf.z, vx, fmaf(cf.w, z.x, -DT * w.x));
            float ey = fmaf(cf.z, vy, fmaf(cf.w, z.y, -DT * w.y));
            acc = fmaf(ex, ex, fmaf(ey, ey, acc));
        }
        vx = fmaf(cf.x, vx, cf.y * z.x);
        vy = fmaf(cf.x, vy, cf.y * z.y);
    }

    for (int o = 16; o; o >>= 1) acc += __shfl_down_sync(0xffffffffu, acc, o);
    __shared__ float swsum[8];
    if ((j & 31) == 0) swsum[j >> 5] = acc;
    __syncthreads();
    if (j < 8) {
        float v = swsum[j];
        v += __shfl_down_sync(0xffu, v, 4);
        v += __shfl_down_sync(0xffu, v, 2);
        v += __shfl_down_sync(0xffu, v, 1);
        if (j == 0) g_partials[bb] = v;
    }
}

__global__ void kf_reduce(float* __restrict__ out, int B, int T) {
    __shared__ float s[256];
    float v = 0.f;
    for (int i = threadIdx.x; i < B; i += blockDim.x) v += g_partials[i];
    s[threadIdx.x] = v;
    __syncthreads();
    for (int o = 128; o; o >>= 1) {
        if (threadIdx.x < o) s[threadIdx.x] += s[threadIdx.x + o];
        __syncthreads();
    }
    if (threadIdx.x == 0)
        out[0] = s[0] / ((float)B * (float)(T - 1) * 2.f);
}

extern "C" void kernel_launch(void* const* d_in, const int* in_sizes, int n_in,
                              void* d_out, int out_size) {
    // metadata order: pred_vel, targ_vel, q_pos, q_vel, r_vel, p0
    const float* pred  = (const float*)d_in[0];
    const float* targ  = (const float*)d_in[1];
    const float* q_vel = (const float*)d_in[3];
    const float* r_vel = (const float*)d_in[4];
    int B = in_sizes[5] / 2;          // p0 is (B, 2)
    int T = in_sizes[0] / (B * 2);    // pred_vel is (B, T, 2)

    if (T == 4096 && B >= 1 && B <= 2048) {
        kf_split<<<2 * B, 128>>>(pred, targ, q_vel, r_vel, (float*)d_out, B);
    } else {
        kf_setup<<<1, 256>>>(q_vel, r_vel, T);
        size_t sh = (size_t)T * sizeof(float2);
        kf_main<<<B, 256, sh>>>(pred, targ, T);
        kf_reduce<<<1, 256>>>((float*)d_out, B, T);
    }
}